// round 12
// baseline (speedup 1.0000x reference)
#include <cuda_runtime.h>
#include <math.h>

#define N 8192
#define D 64
#define ALPHA 0.2f
#define NB 4096          // value bins
#define CAP 64           // member-list capacity per bin
#define NBCH 32          // scan chunks
#define BCH 128          // bins per chunk

// ---------------- scratch ----------------
__device__ float g_h[N * D];
__device__ float g_f1[N];
__device__ float g_f2[N];
__device__ float g_fmin, g_fmax, g_scale;
__device__ float g_binP[NB * D];      // sum of p_j * h_j over bin
__device__ float g_binQ[NB * D];      // sum of q_j * h_j over bin
__device__ float g_bDp[NB], g_bDq[NB];
__device__ int   g_cnt[NB];
__device__ int   g_mIdx[NB * CAP];
__device__ float g_mF2[NB * CAP];
__device__ float g_mP[NB * CAP];      // member p (precomputed exp)
__device__ float g_mQ[NB * CAP];      // member q
__device__ float4 g_rinfo[N];         // per-row {bin(asfloat), A, B, thr}
__device__ float g_csumP[NBCH * D], g_csumQ[NBCH * D];
__device__ float g_csp[NBCH], g_csq[NBCH];
__device__ float g_Cpos[(NB + 1) * D];   // inclusive suffix of binP
__device__ float g_Cneg[(NB + 1) * D];   // exclusive prefix of binQ
__device__ float g_Dpos[NB + 1], g_Dneg[NB + 1];

// monotone-encoded float extrema (reset in k_binscan after consumption)
__device__ unsigned g_encmax = 0u;
__device__ unsigned g_encmin = 0xFFFFFFFFu;

// scan barrier (self-resetting)
__device__ int g_c2 = 0;
__device__ int g_c2done = 0;

__device__ __forceinline__ int bin_of(float v, float fmin, float scale) {
    int b = (int)((v - fmin) * scale);
    return b < 0 ? 0 : (b > NB - 1 ? NB - 1 : b);
}
__device__ __forceinline__ unsigned enc_f(float f) {
    unsigned u = __float_as_uint(f);
    return (u & 0x80000000u) ? ~u : (u | 0x80000000u);
}
__device__ __forceinline__ float dec_f(unsigned e) {
    return (e & 0x80000000u) ? __uint_as_float(e & 0x7FFFFFFFu) : __uint_as_float(~e);
}

// =============== K1: feat (1x4 register tiling) + zero scratch + extrema ===============
// 128 blocks x 1024 threads, 64 rows/block; thread -> row (t>>4), cols 4*(t&15)..+3
__global__ void k_feat(const float* __restrict__ x, const float* __restrict__ Wt,
                       const float* __restrict__ a1, const float* __restrict__ b1,
                       const float* __restrict__ a2, const float* __restrict__ b2) {
    __shared__ float sW[D * D];
    __shared__ float sx[64 * D];

    int t = threadIdx.x;
    int row_base = blockIdx.x * 64;
    int r = t >> 4;              // 0..63 local row
    int og = (t & 15) * 4;       // output col group
    int row = row_base + r;

    // zero this block's slice of bin scratch
    {
        float4 z = make_float4(0.f, 0.f, 0.f, 0.f);
        if (t < 512) {
            ((float4*)g_binP)[blockIdx.x * 512 + t] = z;
            ((float4*)g_binQ)[blockIdx.x * 512 + t] = z;
        }
        if (t < 32) {
            int i = blockIdx.x * 32 + t;
            g_cnt[i] = 0; g_bDp[i] = 0.f; g_bDq[i] = 0.f;
        }
    }

    // load W (4096 floats) and the block's 64 x rows (one shot)
#pragma unroll
    for (int u = 0; u < 4; u++) sW[t + u * 1024] = Wt[t + u * 1024];
    *(float4*)&sx[r * 64 + og] = *(const float4*)&x[row * D + og];
    __syncthreads();

    // h[row][og..og+3] = sum_i x[row][i] * W[i][og..og+3]
    float4 h = make_float4(0.f, 0.f, 0.f, 0.f);
#pragma unroll
    for (int i = 0; i < D; i++) {
        float xv = sx[r * 64 + i];                       // broadcast within 16 lanes
        float4 w = *(const float4*)&sW[i * 64 + og];     // LDS.128
        h.x = fmaf(xv, w.x, h.x);
        h.y = fmaf(xv, w.y, h.y);
        h.z = fmaf(xv, w.z, h.z);
        h.w = fmaf(xv, w.w, h.w);
    }
    *(float4*)&g_h[row * D + og] = h;

    // f1 = h . a1 + b1, f2 = h . a2 + b2 (reduce over 16 lanes)
    float4 va1 = *(const float4*)&a1[og];
    float4 va2 = *(const float4*)&a2[og];
    float v1 = h.x * va1.x + h.y * va1.y + h.z * va1.z + h.w * va1.w;
    float v2 = h.x * va2.x + h.y * va2.y + h.z * va2.z + h.w * va2.w;
#pragma unroll
    for (int s = 8; s; s >>= 1) {
        v1 += __shfl_xor_sync(0xFFFFFFFFu, v1, s);
        v2 += __shfl_xor_sync(0xFFFFFFFFu, v2, s);
    }
    if ((t & 15) == 0) {
        g_f1[row] = v1 + b1[0];
        g_f2[row] = v2 + b2[0];
    }
    __syncthreads();

    // extrema of this block's 64 f2 values (exact, order-independent)
    if (t < 64) {
        float v = g_f2[row_base + t];
        float mx = v, mn = v;
#pragma unroll
        for (int s = 16; s; s >>= 1) {
            mx = fmaxf(mx, __shfl_xor_sync(0xFFFFFFFFu, mx, s));
            mn = fminf(mn, __shfl_xor_sync(0xFFFFFFFFu, mn, s));
        }
        if ((t & 31) == 0) {
            atomicMax(&g_encmax, enc_f(mx));
            atomicMin(&g_encmin, enc_f(mn));
        }
    }
}

// =============== K2: per-bin atomic aggregation + per-row info precompute ===============
// 64 blocks x 256 threads, 128 nodes/block
__global__ void k_binagg() {
    __shared__ int sbin[128];
    __shared__ float sp[128], sq[128];
    __shared__ float scons[4];

    int t = threadIdx.x;
    if (t == 0) {
        float fmax = dec_f(g_encmax);     // final after K1 (kernel boundary)
        float fmin = dec_f(g_encmin);
        float scale = (float)NB / fmaxf(fmax - fmin, 1e-20f);
        scons[0] = fmin; scons[1] = fmax; scons[2] = scale;
        if (blockIdx.x == 0) { g_fmin = fmin; g_fmax = fmax; g_scale = scale; }
    }
    __syncthreads();
    float fmin = scons[0], fmax = scons[1], scale = scons[2];

    int node0 = blockIdx.x * 128;
    if (t < 128) {
        int node = node0 + t;
        float f2 = g_f2[node];
        int b = bin_of(f2, fmin, scale);
        float d = f2 - fmax;
        float pv = expf(d), qv = expf(ALPHA * d);
        sbin[t] = b; sp[t] = pv; sq[t] = qv;
        atomicAdd(&g_bDp[b], pv);
        atomicAdd(&g_bDq[b], qv);
        int c = atomicAdd(&g_cnt[b], 1);
        if (c < CAP) {
            g_mIdx[b * CAP + c] = node;
            g_mF2[b * CAP + c] = f2;
            g_mP[b * CAP + c] = pv;
            g_mQ[b * CAP + c] = qv;
        }
    } else if (t < 256) {
        // per-row output-side precompute: bin of thr, row factors A/B
        int row = node0 + (t - 128);
        float f1 = g_f1[row];
        float s0 = f1 + fmax;
        float e = expf(-(1.0f - ALPHA) * fabsf(s0));
        float A = (s0 >= 0.f) ? 1.0f : e;
        float B = (s0 >= 0.f) ? e : 1.0f;
        float thr = -f1;
        int rb = bin_of(thr, fmin, scale);
        g_rinfo[row] = make_float4(__int_as_float(rb), A, B, thr);
    }
    __syncthreads();

    // 16 threads per node row; float4 loads + float4 atomics (sm_90+)
    int og = (t & 15) * 4;
    int rr = t >> 4;                     // 0..15
#pragma unroll
    for (int m = rr; m < 128; m += 16) {
        float4 hv = *(const float4*)&g_h[(node0 + m) * D + og];   // LDG.128 coalesced
        int b = sbin[m];
        float pv = sp[m], qv = sq[m];
        atomicAdd((float4*)&g_binP[b * D + og],
                  make_float4(pv * hv.x, pv * hv.y, pv * hv.z, pv * hv.w));
        atomicAdd((float4*)&g_binQ[b * D + og],
                  make_float4(qv * hv.x, qv * hv.y, qv * hv.z, qv * hv.w));
    }
}

// =============== K3: bin-level prefix/suffix scan (smem-staged, fused) ===============
// NBCH=32 blocks x 256 threads; dyn smem = 2*BCH*64*4 + 2*BCH*4 = 66.5 KB
__global__ void k_binscan() {
    extern __shared__ float sm2[];
    float* sBP = sm2;                       // BCH*64
    float* sBQ = sm2 + BCH * 64;
    float* sdp = sm2 + 2 * BCH * 64;        // BCH
    float* sdq = sdp + BCH;
    __shared__ float sP[4][64], sQ[4][64], sw[8];

    int t = threadIdx.x;
    int chunk = blockIdx.x;
    int b0 = chunk * BCH;

    if (chunk == 0 && t == 0) {             // extrema consumed by K2; reset for replay
        atomicExch(&g_encmax, 0u);
        atomicExch(&g_encmin, 0xFFFFFFFFu);
    }

    // stage this chunk's bin aggregates (coalesced float4, high MLP)
    {
        const float4* srcP = (const float4*)(g_binP + (size_t)b0 * D);
        const float4* srcQ = (const float4*)(g_binQ + (size_t)b0 * D);
        float4* dP = (float4*)sBP;
        float4* dQ = (float4*)sBQ;
#pragma unroll
        for (int i = t; i < BCH * 16; i += 256) { dP[i] = __ldcg(&srcP[i]); dQ[i] = __ldcg(&srcQ[i]); }
        if (t < BCH) { sdp[t] = __ldcg(&g_bDp[b0 + t]); sdq[t] = __ldcg(&g_bDq[b0 + t]); }
    }
    __syncthreads();

    // chunk sums
    int o = t & 63, r = t >> 6;
    float aP = 0.f, aQ = 0.f;
#pragma unroll 8
    for (int m = r; m < BCH; m += 4) { aP += sBP[m * 64 + o]; aQ += sBQ[m * 64 + o]; }
    sP[r][o] = aP; sQ[r][o] = aQ;

    float spv = 0.f, sqv = 0.f;
    if (t < BCH) { spv = sdp[t]; sqv = sdq[t]; }
#pragma unroll
    for (int s = 16; s; s >>= 1) {
        spv += __shfl_xor_sync(0xFFFFFFFFu, spv, s);
        sqv += __shfl_xor_sync(0xFFFFFFFFu, sqv, s);
    }
    if (t < BCH && (t & 31) == 0) { sw[t >> 5] = spv; sw[4 + (t >> 5)] = sqv; }
    __syncthreads();

    if (r == 0) {
        g_csumP[chunk * 64 + o] = sP[0][o] + sP[1][o] + sP[2][o] + sP[3][o];
        g_csumQ[chunk * 64 + o] = sQ[0][o] + sQ[1][o] + sQ[2][o] + sQ[3][o];
    }
    if (t == 0) {
        g_csp[chunk] = sw[0] + sw[1] + sw[2] + sw[3];
        g_csq[chunk] = sw[4] + sw[5] + sw[6] + sw[7];
    }

    // grid barrier (32 blocks, all resident)
    __syncthreads();
    __threadfence();
    if (t == 0) {
        atomicAdd(&g_c2, 1);
        while (atomicAdd(&g_c2, 0) < NBCH) __nanosleep(64);
    }
    __syncthreads();

    // walks
    if (t < 64) {
        float off = 0.f;
#pragma unroll
        for (int c = 0; c < NBCH; c++) {
            float v = __ldcg(&g_csumQ[c * 64 + t]);
            if (c < chunk) off += v;
        }
        float run = off;
#pragma unroll 8
        for (int m = 0; m < BCH; m++) {
            g_Cneg[(size_t)(b0 + m) * D + t] = run;
            run += sBQ[m * 64 + t];
        }
        if (chunk == NBCH - 1) g_Cneg[(size_t)NB * D + t] = run;
    } else if (t < 128) {
        int c0 = t - 64;
        float off = 0.f;
#pragma unroll
        for (int c = 0; c < NBCH; c++) {
            float v = __ldcg(&g_csumP[c * 64 + c0]);
            if (c > chunk) off += v;
        }
        float run = off;
        if (chunk == NBCH - 1) g_Cpos[(size_t)NB * D + c0] = 0.f;
#pragma unroll 8
        for (int m = BCH - 1; m >= 0; m--) {
            run += sBP[m * 64 + c0];
            g_Cpos[(size_t)(b0 + m) * D + c0] = run;
        }
    } else if (t == 128) {
        float off = 0.f;
#pragma unroll
        for (int c = 0; c < NBCH; c++) { float v = __ldcg(&g_csq[c]); if (c < chunk) off += v; }
        float run = off;
        for (int m = 0; m < BCH; m++) { g_Dneg[b0 + m] = run; run += sdq[m]; }
        if (chunk == NBCH - 1) g_Dneg[NB] = run;
    } else if (t == 129) {
        float off = 0.f;
#pragma unroll
        for (int c = 0; c < NBCH; c++) { float v = __ldcg(&g_csp[c]); if (c > chunk) off += v; }
        float run = off;
        if (chunk == NBCH - 1) g_Dpos[NB] = 0.f;
        for (int m = BCH - 1; m >= 0; m--) { run += sdp[m]; g_Dpos[b0 + m] = run; }
    }

    // replay-safe counter reset
    __syncthreads();
    if (t == 0) {
        int d = atomicAdd(&g_c2done, 1);
        if (d == NBCH - 1) { atomicExch(&g_c2, 0); atomicExch(&g_c2done, 0); }
    }
}

// =============== K4: per-row combine, 2 rows/thread (interleaved chains) ===============
// 256 blocks x 256 threads; 32 rows/block: thread handles rows r0 and r0+16
__global__ void k_out(float* __restrict__ out) {
    int t = threadIdx.x;
    int og = (t & 15) * 4;
    int r0 = blockIdx.x * 32 + (t >> 4);
    int r1 = r0 + 16;

    // independent heads: 2 LDG.128 in flight immediately
    float4 i0 = g_rinfo[r0];
    float4 i1 = g_rinfo[r1];

    int   b0 = __float_as_int(i0.x);
    float A0 = i0.y, B0 = i0.z, thr0 = i0.w;
    int   b1 = __float_as_int(i1.x);
    float A1 = i1.y, B1 = i1.z, thr1 = i1.w;

    // fan out all bin-indexed loads for both rows
    float4 cp0 = *(const float4*)&g_Cpos[(size_t)(b0 + 1) * D + og];
    float4 cn0 = *(const float4*)&g_Cneg[(size_t)b0 * D + og];
    float4 cp1 = *(const float4*)&g_Cpos[(size_t)(b1 + 1) * D + og];
    float4 cn1 = *(const float4*)&g_Cneg[(size_t)b1 * D + og];
    float dp0 = g_Dpos[b0 + 1], dn0 = g_Dneg[b0];
    float dp1 = g_Dpos[b1 + 1], dn1 = g_Dneg[b1];
    int cnt0 = g_cnt[b0]; if (cnt0 > CAP) cnt0 = CAP;
    int cnt1 = g_cnt[b1]; if (cnt1 > CAP) cnt1 = CAP;

    float4 num0 = make_float4(A0 * cp0.x + B0 * cn0.x, A0 * cp0.y + B0 * cn0.y,
                              A0 * cp0.z + B0 * cn0.z, A0 * cp0.w + B0 * cn0.w);
    float4 num1 = make_float4(A1 * cp1.x + B1 * cn1.x, A1 * cp1.y + B1 * cn1.y,
                              A1 * cp1.z + B1 * cn1.z, A1 * cp1.w + B1 * cn1.w);
    float den0 = A0 * dp0 + B0 * dn0;
    float den1 = A1 * dp1 + B1 * dn1;

    for (int j = 0; j < cnt0; j++) {
        int idx = g_mIdx[b0 * CAP + j];
        float f2j = g_mF2[b0 * CAP + j];
        float4 hv = *(const float4*)&g_h[(size_t)idx * D + og];
        float w = (f2j >= thr0) ? A0 * g_mP[b0 * CAP + j] : B0 * g_mQ[b0 * CAP + j];
        num0.x = fmaf(w, hv.x, num0.x);
        num0.y = fmaf(w, hv.y, num0.y);
        num0.z = fmaf(w, hv.z, num0.z);
        num0.w = fmaf(w, hv.w, num0.w);
        den0 += w;
    }
    for (int j = 0; j < cnt1; j++) {
        int idx = g_mIdx[b1 * CAP + j];
        float f2j = g_mF2[b1 * CAP + j];
        float4 hv = *(const float4*)&g_h[(size_t)idx * D + og];
        float w = (f2j >= thr1) ? A1 * g_mP[b1 * CAP + j] : B1 * g_mQ[b1 * CAP + j];
        num1.x = fmaf(w, hv.x, num1.x);
        num1.y = fmaf(w, hv.y, num1.y);
        num1.z = fmaf(w, hv.z, num1.z);
        num1.w = fmaf(w, hv.w, num1.w);
        den1 += w;
    }

    float inv0 = 1.0f / den0;
    float inv1 = 1.0f / den1;
    float4 o0, o1;
    float rx;
    rx = num0.x * inv0; o0.x = (rx > 0.f) ? rx : expm1f(rx);
    rx = num0.y * inv0; o0.y = (rx > 0.f) ? rx : expm1f(rx);
    rx = num0.z * inv0; o0.z = (rx > 0.f) ? rx : expm1f(rx);
    rx = num0.w * inv0; o0.w = (rx > 0.f) ? rx : expm1f(rx);
    rx = num1.x * inv1; o1.x = (rx > 0.f) ? rx : expm1f(rx);
    rx = num1.y * inv1; o1.y = (rx > 0.f) ? rx : expm1f(rx);
    rx = num1.z * inv1; o1.z = (rx > 0.f) ? rx : expm1f(rx);
    rx = num1.w * inv1; o1.w = (rx > 0.f) ? rx : expm1f(rx);
    *(float4*)&out[(size_t)r0 * D + og] = o0;
    *(float4*)&out[(size_t)r1 * D + og] = o1;
}

// ---------------- launch ----------------
extern "C" void kernel_launch(void* const* d_in, const int* in_sizes, int n_in,
                              void* d_out, int out_size) {
    const float* x  = (const float*)d_in[0];
    const float* Wt = (const float*)d_in[1];
    const float* a1 = (const float*)d_in[2];
    const float* b1 = (const float*)d_in[3];
    const float* a2 = (const float*)d_in[4];
    const float* b2 = (const float*)d_in[5];
    float* out = (float*)d_out;

    const int smem_scan = (2 * BCH * 64 + 2 * BCH) * 4;   // 66.5 KB

    static bool attr_set = false;
    if (!attr_set) {
        cudaFuncSetAttribute(k_binscan, cudaFuncAttributeMaxDynamicSharedMemorySize, smem_scan);
        attr_set = true;
    }

    k_feat<<<128, 1024>>>(x, Wt, a1, b1, a2, b2);
    k_binagg<<<64, 256>>>();
    k_binscan<<<NBCH, 256, smem_scan>>>();
    k_out<<<256, 256>>>(out);
}

// round 14
// speedup vs baseline: 1.1491x; 1.1491x over previous
#include <cuda_runtime.h>
#include <math.h>

#define N 8192
#define D 64
#define ALPHA 0.2f
#define NB 4096          // value bins
#define CAP 64           // member-list capacity per bin
#define NBCH 32          // scan chunks
#define BCH 128          // bins per chunk

// ---------------- scratch ----------------
__device__ float g_h[N * D];
__device__ float g_f1[N];
__device__ float g_f2[N];
__device__ float g_fmin, g_fmax, g_scale;
__device__ float g_binP[NB * D];      // sum of p_j * h_j over bin
__device__ float g_binQ[NB * D];      // sum of q_j * h_j over bin
__device__ float g_bDp[NB], g_bDq[NB];
__device__ int   g_cnt[NB];
__device__ int   g_mIdx[NB * CAP];
__device__ float g_mF2[NB * CAP];
__device__ float g_mP[NB * CAP];      // member p (precomputed exp)
__device__ float g_mQ[NB * CAP];      // member q
__device__ float4 g_rinfo[N];         // per-row {bin(asfloat), A, B, thr}
__device__ float g_csumP[NBCH * D], g_csumQ[NBCH * D];
__device__ float g_csp[NBCH], g_csq[NBCH];
__device__ float g_Cpos[(NB + 1) * D];   // inclusive suffix of binP
__device__ float g_Cneg[(NB + 1) * D];   // exclusive prefix of binQ
__device__ float g_Dpos[NB + 1], g_Dneg[NB + 1];

// monotone-encoded float extrema (reset in k_binscan after consumption)
__device__ unsigned g_encmax = 0u;
__device__ unsigned g_encmin = 0xFFFFFFFFu;

// scan barrier (self-resetting)
__device__ int g_c2 = 0;
__device__ int g_c2done = 0;

__device__ __forceinline__ int bin_of(float v, float fmin, float scale) {
    int b = (int)((v - fmin) * scale);
    return b < 0 ? 0 : (b > NB - 1 ? NB - 1 : b);
}
__device__ __forceinline__ unsigned enc_f(float f) {
    unsigned u = __float_as_uint(f);
    return (u & 0x80000000u) ? ~u : (u | 0x80000000u);
}
__device__ __forceinline__ float dec_f(unsigned e) {
    return (e & 0x80000000u) ? __uint_as_float(e & 0x7FFFFFFFu) : __uint_as_float(~e);
}

// =============== K1: feat (1x4 register tiling) + zero scratch + extrema ===============
// 128 blocks x 1024 threads, 64 rows/block; thread -> row (t>>4), cols 4*(t&15)..+3
__global__ void k_feat(const float* __restrict__ x, const float* __restrict__ Wt,
                       const float* __restrict__ a1, const float* __restrict__ b1,
                       const float* __restrict__ a2, const float* __restrict__ b2) {
    __shared__ float sW[D * D];
    __shared__ float sx[64 * D];

    int t = threadIdx.x;
    int row_base = blockIdx.x * 64;
    int r = t >> 4;              // 0..63 local row
    int og = (t & 15) * 4;       // output col group
    int row = row_base + r;

    // zero this block's slice of bin scratch
    {
        float4 z = make_float4(0.f, 0.f, 0.f, 0.f);
        if (t < 512) {
            ((float4*)g_binP)[blockIdx.x * 512 + t] = z;
            ((float4*)g_binQ)[blockIdx.x * 512 + t] = z;
        }
        if (t < 32) {
            int i = blockIdx.x * 32 + t;
            g_cnt[i] = 0; g_bDp[i] = 0.f; g_bDq[i] = 0.f;
        }
    }

    // load W (4096 floats) and the block's 64 x rows (one shot)
#pragma unroll
    for (int u = 0; u < 4; u++) sW[t + u * 1024] = Wt[t + u * 1024];
    *(float4*)&sx[r * 64 + og] = *(const float4*)&x[row * D + og];
    __syncthreads();

    // h[row][og..og+3] = sum_i x[row][i] * W[i][og..og+3]
    float4 h = make_float4(0.f, 0.f, 0.f, 0.f);
#pragma unroll
    for (int i = 0; i < D; i++) {
        float xv = sx[r * 64 + i];                       // broadcast within 16 lanes
        float4 w = *(const float4*)&sW[i * 64 + og];     // LDS.128
        h.x = fmaf(xv, w.x, h.x);
        h.y = fmaf(xv, w.y, h.y);
        h.z = fmaf(xv, w.z, h.z);
        h.w = fmaf(xv, w.w, h.w);
    }
    *(float4*)&g_h[row * D + og] = h;

    // f1 = h . a1 + b1, f2 = h . a2 + b2 (reduce over 16 lanes)
    float4 va1 = *(const float4*)&a1[og];
    float4 va2 = *(const float4*)&a2[og];
    float v1 = h.x * va1.x + h.y * va1.y + h.z * va1.z + h.w * va1.w;
    float v2 = h.x * va2.x + h.y * va2.y + h.z * va2.z + h.w * va2.w;
#pragma unroll
    for (int s = 8; s; s >>= 1) {
        v1 += __shfl_xor_sync(0xFFFFFFFFu, v1, s);
        v2 += __shfl_xor_sync(0xFFFFFFFFu, v2, s);
    }
    if ((t & 15) == 0) {
        g_f1[row] = v1 + b1[0];
        g_f2[row] = v2 + b2[0];
    }
    __syncthreads();

    // extrema of this block's 64 f2 values (exact, order-independent)
    if (t < 64) {
        float v = g_f2[row_base + t];
        float mx = v, mn = v;
#pragma unroll
        for (int s = 16; s; s >>= 1) {
            mx = fmaxf(mx, __shfl_xor_sync(0xFFFFFFFFu, mx, s));
            mn = fminf(mn, __shfl_xor_sync(0xFFFFFFFFu, mn, s));
        }
        if ((t & 31) == 0) {
            atomicMax(&g_encmax, enc_f(mx));
            atomicMin(&g_encmin, enc_f(mn));
        }
    }
}

// =============== K2: per-bin atomic aggregation + per-row info precompute ===============
// 64 blocks x 256 threads, 128 nodes/block
__global__ void k_binagg() {
    __shared__ int sbin[128];
    __shared__ float sp[128], sq[128];
    __shared__ float scons[4];

    int t = threadIdx.x;
    if (t == 0) {
        float fmax = dec_f(g_encmax);     // final after K1 (kernel boundary)
        float fmin = dec_f(g_encmin);
        float scale = (float)NB / fmaxf(fmax - fmin, 1e-20f);
        scons[0] = fmin; scons[1] = fmax; scons[2] = scale;
        if (blockIdx.x == 0) { g_fmin = fmin; g_fmax = fmax; g_scale = scale; }
    }
    __syncthreads();
    float fmin = scons[0], fmax = scons[1], scale = scons[2];

    int node0 = blockIdx.x * 128;
    if (t < 128) {
        int node = node0 + t;
        float f2 = g_f2[node];
        int b = bin_of(f2, fmin, scale);
        float d = f2 - fmax;
        float pv = expf(d), qv = expf(ALPHA * d);
        sbin[t] = b; sp[t] = pv; sq[t] = qv;
        atomicAdd(&g_bDp[b], pv);
        atomicAdd(&g_bDq[b], qv);
        int c = atomicAdd(&g_cnt[b], 1);
        if (c < CAP) {
            g_mIdx[b * CAP + c] = node;
            g_mF2[b * CAP + c] = f2;
            g_mP[b * CAP + c] = pv;
            g_mQ[b * CAP + c] = qv;
        }
    } else if (t < 256) {
        // per-row output-side precompute: bin of thr, row factors A/B
        int row = node0 + (t - 128);
        float f1 = g_f1[row];
        float s0 = f1 + fmax;
        float e = expf(-(1.0f - ALPHA) * fabsf(s0));
        float A = (s0 >= 0.f) ? 1.0f : e;
        float B = (s0 >= 0.f) ? e : 1.0f;
        float thr = -f1;
        int rb = bin_of(thr, fmin, scale);
        g_rinfo[row] = make_float4(__int_as_float(rb), A, B, thr);
    }
    __syncthreads();

    // 16 threads per node row; float4 loads + float4 atomics (sm_90+)
    int og = (t & 15) * 4;
    int rr = t >> 4;                     // 0..15
#pragma unroll
    for (int m = rr; m < 128; m += 16) {
        float4 hv = *(const float4*)&g_h[(node0 + m) * D + og];   // LDG.128 coalesced
        int b = sbin[m];
        float pv = sp[m], qv = sq[m];
        atomicAdd((float4*)&g_binP[b * D + og],
                  make_float4(pv * hv.x, pv * hv.y, pv * hv.z, pv * hv.w));
        atomicAdd((float4*)&g_binQ[b * D + og],
                  make_float4(qv * hv.x, qv * hv.y, qv * hv.z, qv * hv.w));
    }
}

// =============== K3: bin-level prefix/suffix scan (smem-staged, fused) ===============
// NBCH=32 blocks x 256 threads; dyn smem = 2*BCH*64*4 + 2*BCH*4 = 66.5 KB
__global__ void k_binscan() {
    extern __shared__ float sm2[];
    float* sBP = sm2;                       // BCH*64
    float* sBQ = sm2 + BCH * 64;
    float* sdp = sm2 + 2 * BCH * 64;        // BCH
    float* sdq = sdp + BCH;
    __shared__ float sP[4][64], sQ[4][64], sw[8];

    int t = threadIdx.x;
    int chunk = blockIdx.x;
    int b0 = chunk * BCH;

    if (chunk == 0 && t == 0) {             // extrema consumed by K2; reset for replay
        atomicExch(&g_encmax, 0u);
        atomicExch(&g_encmin, 0xFFFFFFFFu);
    }

    // stage this chunk's bin aggregates (coalesced float4, high MLP)
    {
        const float4* srcP = (const float4*)(g_binP + (size_t)b0 * D);
        const float4* srcQ = (const float4*)(g_binQ + (size_t)b0 * D);
        float4* dP = (float4*)sBP;
        float4* dQ = (float4*)sBQ;
#pragma unroll
        for (int i = t; i < BCH * 16; i += 256) { dP[i] = __ldcg(&srcP[i]); dQ[i] = __ldcg(&srcQ[i]); }
        if (t < BCH) { sdp[t] = __ldcg(&g_bDp[b0 + t]); sdq[t] = __ldcg(&g_bDq[b0 + t]); }
    }
    __syncthreads();

    // chunk sums
    int o = t & 63, r = t >> 6;
    float aP = 0.f, aQ = 0.f;
#pragma unroll 8
    for (int m = r; m < BCH; m += 4) { aP += sBP[m * 64 + o]; aQ += sBQ[m * 64 + o]; }
    sP[r][o] = aP; sQ[r][o] = aQ;

    float spv = 0.f, sqv = 0.f;
    if (t < BCH) { spv = sdp[t]; sqv = sdq[t]; }
#pragma unroll
    for (int s = 16; s; s >>= 1) {
        spv += __shfl_xor_sync(0xFFFFFFFFu, spv, s);
        sqv += __shfl_xor_sync(0xFFFFFFFFu, sqv, s);
    }
    if (t < BCH && (t & 31) == 0) { sw[t >> 5] = spv; sw[4 + (t >> 5)] = sqv; }
    __syncthreads();

    if (r == 0) {
        g_csumP[chunk * 64 + o] = sP[0][o] + sP[1][o] + sP[2][o] + sP[3][o];
        g_csumQ[chunk * 64 + o] = sQ[0][o] + sQ[1][o] + sQ[2][o] + sQ[3][o];
    }
    if (t == 0) {
        g_csp[chunk] = sw[0] + sw[1] + sw[2] + sw[3];
        g_csq[chunk] = sw[4] + sw[5] + sw[6] + sw[7];
    }

    // grid barrier (32 blocks, all resident)
    __syncthreads();
    __threadfence();
    if (t == 0) {
        atomicAdd(&g_c2, 1);
        while (atomicAdd(&g_c2, 0) < NBCH) __nanosleep(64);
    }
    __syncthreads();

    // walks
    if (t < 64) {
        float off = 0.f;
#pragma unroll
        for (int c = 0; c < NBCH; c++) {
            float v = __ldcg(&g_csumQ[c * 64 + t]);
            if (c < chunk) off += v;
        }
        float run = off;
#pragma unroll 8
        for (int m = 0; m < BCH; m++) {
            g_Cneg[(size_t)(b0 + m) * D + t] = run;
            run += sBQ[m * 64 + t];
        }
        if (chunk == NBCH - 1) g_Cneg[(size_t)NB * D + t] = run;
    } else if (t < 128) {
        int c0 = t - 64;
        float off = 0.f;
#pragma unroll
        for (int c = 0; c < NBCH; c++) {
            float v = __ldcg(&g_csumP[c * 64 + c0]);
            if (c > chunk) off += v;
        }
        float run = off;
        if (chunk == NBCH - 1) g_Cpos[(size_t)NB * D + c0] = 0.f;
#pragma unroll 8
        for (int m = BCH - 1; m >= 0; m--) {
            run += sBP[m * 64 + c0];
            g_Cpos[(size_t)(b0 + m) * D + c0] = run;
        }
    } else if (t == 128) {
        float off = 0.f;
#pragma unroll
        for (int c = 0; c < NBCH; c++) { float v = __ldcg(&g_csq[c]); if (c < chunk) off += v; }
        float run = off;
        for (int m = 0; m < BCH; m++) { g_Dneg[b0 + m] = run; run += sdq[m]; }
        if (chunk == NBCH - 1) g_Dneg[NB] = run;
    } else if (t == 129) {
        float off = 0.f;
#pragma unroll
        for (int c = 0; c < NBCH; c++) { float v = __ldcg(&g_csp[c]); if (c > chunk) off += v; }
        float run = off;
        if (chunk == NBCH - 1) g_Dpos[NB] = 0.f;
        for (int m = BCH - 1; m >= 0; m--) { run += sdp[m]; g_Dpos[b0 + m] = run; }
    }

    // replay-safe counter reset
    __syncthreads();
    if (t == 0) {
        int d = atomicAdd(&g_c2done, 1);
        if (d == NBCH - 1) { atomicExch(&g_c2, 0); atomicExch(&g_c2done, 0); }
    }
}

// =============== K4: per-row combine (32 threads/row, float2) ===============
// 1024 blocks x 256 threads; 8 rows/block, 1 row/thread-group
__global__ void __launch_bounds__(256, 6) k_out(float* __restrict__ out) {
    int t = threadIdx.x;
    int og = (t & 31) * 2;               // column pair
    int row = blockIdx.x * 8 + (t >> 5);

    float4 inf = g_rinfo[row];
    int   b   = __float_as_int(inf.x);
    float A   = inf.y, B = inf.z, thr = inf.w;

    float2 cp = *(const float2*)&g_Cpos[(size_t)(b + 1) * D + og];
    float2 cn = *(const float2*)&g_Cneg[(size_t)b * D + og];
    float dp = g_Dpos[b + 1], dn = g_Dneg[b];
    int cnt = g_cnt[b]; if (cnt > CAP) cnt = CAP;

    float2 num = make_float2(A * cp.x + B * cn.x, A * cp.y + B * cn.y);
    float den = A * dp + B * dn;

    for (int j = 0; j < cnt; j++) {      // exact compares within boundary bin
        int idx = g_mIdx[b * CAP + j];           // broadcast loads within 32 lanes
        float f2j = g_mF2[b * CAP + j];
        float2 hv = *(const float2*)&g_h[(size_t)idx * D + og];
        float w = (f2j >= thr) ? A * g_mP[b * CAP + j] : B * g_mQ[b * CAP + j];
        num.x = fmaf(w, hv.x, num.x);
        num.y = fmaf(w, hv.y, num.y);
        den += w;
    }

    float inv = 1.0f / den;
    float2 o2;
    float rx;
    rx = num.x * inv; o2.x = (rx > 0.f) ? rx : expm1f(rx);
    rx = num.y * inv; o2.y = (rx > 0.f) ? rx : expm1f(rx);
    *(float2*)&out[(size_t)row * D + og] = o2;
}

// ---------------- launch ----------------
extern "C" void kernel_launch(void* const* d_in, const int* in_sizes, int n_in,
                              void* d_out, int out_size) {
    const float* x  = (const float*)d_in[0];
    const float* Wt = (const float*)d_in[1];
    const float* a1 = (const float*)d_in[2];
    const float* b1 = (const float*)d_in[3];
    const float* a2 = (const float*)d_in[4];
    const float* b2 = (const float*)d_in[5];
    float* out = (float*)d_out;

    const int smem_scan = (2 * BCH * 64 + 2 * BCH) * 4;   // 66.5 KB

    static bool attr_set = false;
    if (!attr_set) {
        cudaFuncSetAttribute(k_binscan, cudaFuncAttributeMaxDynamicSharedMemorySize, smem_scan);
        attr_set = true;
    }

    k_feat<<<128, 1024>>>(x, Wt, a1, b1, a2, b2);
    k_binagg<<<64, 256>>>();
    k_binscan<<<NBCH, 256, smem_scan>>>();
    k_out<<<1024, 256>>>(out);
}

// round 16
// speedup vs baseline: 1.1504x; 1.0011x over previous
#include <cuda_runtime.h>
#include <math.h>

#define N 8192
#define D 64
#define ALPHA 0.2f
#define NB 4096          // value bins
#define CAP 64           // member-list capacity per bin
#define NBCH 64          // scan chunks
#define BCH 64           // bins per chunk

// ---------------- scratch ----------------
__device__ float g_h[N * D];
__device__ float g_f1[N];
__device__ float g_f2[N];
__device__ float g_fmin, g_fmax, g_scale;
__device__ float g_binP[NB * D];      // sum of p_j * h_j over bin
__device__ float g_binQ[NB * D];      // sum of q_j * h_j over bin
__device__ float g_bDp[NB], g_bDq[NB];
__device__ int   g_cnt[NB];
__device__ float4 g_mPack[NB * CAP];  // member {idx(asfloat), f2, p, q}
__device__ float4 g_rinfo[N];         // per-row {bin(asfloat), A, B, thr}
__device__ float g_csumP[NBCH * D], g_csumQ[NBCH * D];
__device__ float g_csp[NBCH], g_csq[NBCH];
__device__ float g_Cpos[(NB + 1) * D];   // inclusive suffix of binP
__device__ float g_Cneg[(NB + 1) * D];   // exclusive prefix of binQ
__device__ float g_Dpos[NB + 1], g_Dneg[NB + 1];

// monotone-encoded float extrema (reset in k_binscan after consumption)
__device__ unsigned g_encmax = 0u;
__device__ unsigned g_encmin = 0xFFFFFFFFu;

// scan barrier (self-resetting)
__device__ int g_c2 = 0;
__device__ int g_c2done = 0;

__device__ __forceinline__ int bin_of(float v, float fmin, float scale) {
    int b = (int)((v - fmin) * scale);
    return b < 0 ? 0 : (b > NB - 1 ? NB - 1 : b);
}
__device__ __forceinline__ unsigned enc_f(float f) {
    unsigned u = __float_as_uint(f);
    return (u & 0x80000000u) ? ~u : (u | 0x80000000u);
}
__device__ __forceinline__ float dec_f(unsigned e) {
    return (e & 0x80000000u) ? __uint_as_float(e & 0x7FFFFFFFu) : __uint_as_float(~e);
}

// =============== K1: feat (1x4 register tiling) + zero scratch + extrema ===============
// 128 blocks x 1024 threads, 64 rows/block; thread -> row (t>>4), cols 4*(t&15)..+3
__global__ void k_feat(const float* __restrict__ x, const float* __restrict__ Wt,
                       const float* __restrict__ a1, const float* __restrict__ b1,
                       const float* __restrict__ a2, const float* __restrict__ b2) {
    __shared__ float sW[D * D];
    __shared__ float sx[64 * D];

    int t = threadIdx.x;
    int row_base = blockIdx.x * 64;
    int r = t >> 4;              // 0..63 local row
    int og = (t & 15) * 4;       // output col group
    int row = row_base + r;

    // zero this block's slice of bin scratch
    {
        float4 z = make_float4(0.f, 0.f, 0.f, 0.f);
        if (t < 512) {
            ((float4*)g_binP)[blockIdx.x * 512 + t] = z;
            ((float4*)g_binQ)[blockIdx.x * 512 + t] = z;
        }
        if (t < 32) {
            int i = blockIdx.x * 32 + t;
            g_cnt[i] = 0; g_bDp[i] = 0.f; g_bDq[i] = 0.f;
        }
    }

    // load W (4096 floats) and the block's 64 x rows (one shot)
#pragma unroll
    for (int u = 0; u < 4; u++) sW[t + u * 1024] = Wt[t + u * 1024];
    *(float4*)&sx[r * 64 + og] = *(const float4*)&x[row * D + og];
    __syncthreads();

    // h[row][og..og+3] = sum_i x[row][i] * W[i][og..og+3]
    float4 h = make_float4(0.f, 0.f, 0.f, 0.f);
#pragma unroll
    for (int i = 0; i < D; i++) {
        float xv = sx[r * 64 + i];                       // broadcast within 16 lanes
        float4 w = *(const float4*)&sW[i * 64 + og];     // LDS.128
        h.x = fmaf(xv, w.x, h.x);
        h.y = fmaf(xv, w.y, h.y);
        h.z = fmaf(xv, w.z, h.z);
        h.w = fmaf(xv, w.w, h.w);
    }
    *(float4*)&g_h[row * D + og] = h;

    // f1 = h . a1 + b1, f2 = h . a2 + b2 (reduce over 16 lanes)
    float4 va1 = *(const float4*)&a1[og];
    float4 va2 = *(const float4*)&a2[og];
    float v1 = h.x * va1.x + h.y * va1.y + h.z * va1.z + h.w * va1.w;
    float v2 = h.x * va2.x + h.y * va2.y + h.z * va2.z + h.w * va2.w;
#pragma unroll
    for (int s = 8; s; s >>= 1) {
        v1 += __shfl_xor_sync(0xFFFFFFFFu, v1, s);
        v2 += __shfl_xor_sync(0xFFFFFFFFu, v2, s);
    }
    if ((t & 15) == 0) {
        g_f1[row] = v1 + b1[0];
        g_f2[row] = v2 + b2[0];
    }
    __syncthreads();

    // extrema of this block's 64 f2 values (exact, order-independent)
    if (t < 64) {
        float v = g_f2[row_base + t];
        float mx = v, mn = v;
#pragma unroll
        for (int s = 16; s; s >>= 1) {
            mx = fmaxf(mx, __shfl_xor_sync(0xFFFFFFFFu, mx, s));
            mn = fminf(mn, __shfl_xor_sync(0xFFFFFFFFu, mn, s));
        }
        if ((t & 31) == 0) {
            atomicMax(&g_encmax, enc_f(mx));
            atomicMin(&g_encmin, enc_f(mn));
        }
    }
}

// =============== K2: per-bin atomic aggregation + per-row info precompute ===============
// 64 blocks x 256 threads, 128 nodes/block
__global__ void k_binagg() {
    __shared__ int sbin[128];
    __shared__ float sp[128], sq[128];
    __shared__ float scons[4];

    int t = threadIdx.x;
    if (t == 0) {
        float fmax = dec_f(g_encmax);     // final after K1 (kernel boundary)
        float fmin = dec_f(g_encmin);
        float scale = (float)NB / fmaxf(fmax - fmin, 1e-20f);
        scons[0] = fmin; scons[1] = fmax; scons[2] = scale;
        if (blockIdx.x == 0) { g_fmin = fmin; g_fmax = fmax; g_scale = scale; }
    }
    __syncthreads();
    float fmin = scons[0], fmax = scons[1], scale = scons[2];

    int node0 = blockIdx.x * 128;
    if (t < 128) {
        int node = node0 + t;
        float f2 = g_f2[node];
        int b = bin_of(f2, fmin, scale);
        float d = f2 - fmax;
        float pv = expf(d), qv = expf(ALPHA * d);
        sbin[t] = b; sp[t] = pv; sq[t] = qv;
        atomicAdd(&g_bDp[b], pv);
        atomicAdd(&g_bDq[b], qv);
        int c = atomicAdd(&g_cnt[b], 1);
        if (c < CAP) {
            g_mPack[b * CAP + c] = make_float4(__int_as_float(node), f2, pv, qv);
        }
    } else if (t < 256) {
        // per-row output-side precompute: bin of thr, row factors A/B
        int row = node0 + (t - 128);
        float f1 = g_f1[row];
        float s0 = f1 + fmax;
        float e = expf(-(1.0f - ALPHA) * fabsf(s0));
        float A = (s0 >= 0.f) ? 1.0f : e;
        float B = (s0 >= 0.f) ? e : 1.0f;
        float thr = -f1;
        int rb = bin_of(thr, fmin, scale);
        g_rinfo[row] = make_float4(__int_as_float(rb), A, B, thr);
    }
    __syncthreads();

    // 16 threads per node row; float4 loads + float4 atomics (sm_90+)
    int og = (t & 15) * 4;
    int rr = t >> 4;                     // 0..15
#pragma unroll
    for (int m = rr; m < 128; m += 16) {
        float4 hv = *(const float4*)&g_h[(node0 + m) * D + og];   // LDG.128 coalesced
        int b = sbin[m];
        float pv = sp[m], qv = sq[m];
        atomicAdd((float4*)&g_binP[b * D + og],
                  make_float4(pv * hv.x, pv * hv.y, pv * hv.z, pv * hv.w));
        atomicAdd((float4*)&g_binQ[b * D + og],
                  make_float4(qv * hv.x, qv * hv.y, qv * hv.z, qv * hv.w));
    }
}

// =============== K3: bin-level prefix/suffix scan (smem-staged, fused) ===============
// NBCH=64 blocks x 256 threads; dyn smem = (2*BCH*64 + 2*BCH)*4 = 33.3 KB
__global__ void k_binscan() {
    extern __shared__ float sm2[];
    float* sBP = sm2;                       // BCH*64
    float* sBQ = sm2 + BCH * 64;
    float* sdp = sm2 + 2 * BCH * 64;        // BCH
    float* sdq = sdp + BCH;
    __shared__ float sP[4][64], sQ[4][64], sw[8];

    int t = threadIdx.x;
    int chunk = blockIdx.x;
    int b0 = chunk * BCH;

    if (chunk == 0 && t == 0) {             // extrema consumed by K2; reset for replay
        atomicExch(&g_encmax, 0u);
        atomicExch(&g_encmin, 0xFFFFFFFFu);
    }

    // stage this chunk's bin aggregates (coalesced float4, high MLP)
    {
        const float4* srcP = (const float4*)(g_binP + (size_t)b0 * D);
        const float4* srcQ = (const float4*)(g_binQ + (size_t)b0 * D);
        float4* dP = (float4*)sBP;
        float4* dQ = (float4*)sBQ;
#pragma unroll
        for (int i = t; i < BCH * 16; i += 256) { dP[i] = __ldcg(&srcP[i]); dQ[i] = __ldcg(&srcQ[i]); }
        if (t < BCH) { sdp[t] = __ldcg(&g_bDp[b0 + t]); sdq[t] = __ldcg(&g_bDq[b0 + t]); }
    }
    __syncthreads();

    // chunk sums
    int o = t & 63, r = t >> 6;
    float aP = 0.f, aQ = 0.f;
#pragma unroll
    for (int m = r; m < BCH; m += 4) { aP += sBP[m * 64 + o]; aQ += sBQ[m * 64 + o]; }
    sP[r][o] = aP; sQ[r][o] = aQ;

    float spv = 0.f, sqv = 0.f;
    if (t < BCH) { spv = sdp[t]; sqv = sdq[t]; }
#pragma unroll
    for (int s = 16; s; s >>= 1) {
        spv += __shfl_xor_sync(0xFFFFFFFFu, spv, s);
        sqv += __shfl_xor_sync(0xFFFFFFFFu, sqv, s);
    }
    if (t < BCH && (t & 31) == 0) { sw[t >> 5] = spv; sw[4 + (t >> 5)] = sqv; }
    __syncthreads();

    if (r == 0) {
        g_csumP[chunk * 64 + o] = sP[0][o] + sP[1][o] + sP[2][o] + sP[3][o];
        g_csumQ[chunk * 64 + o] = sQ[0][o] + sQ[1][o] + sQ[2][o] + sQ[3][o];
    }
    if (t == 0) {
        g_csp[chunk] = sw[0] + sw[1];
        g_csq[chunk] = sw[4] + sw[5];
    }

    // grid barrier (64 blocks, all resident: 33KB smem -> 2 blocks/SM)
    __syncthreads();
    __threadfence();
    if (t == 0) {
        atomicAdd(&g_c2, 1);
        while (atomicAdd(&g_c2, 0) < NBCH) __nanosleep(64);
    }
    __syncthreads();

    // walks (64 serial iters per block)
    if (t < 64) {
        float off = 0.f;
#pragma unroll
        for (int c = 0; c < NBCH; c++) {
            float v = __ldcg(&g_csumQ[c * 64 + t]);
            if (c < chunk) off += v;
        }
        float run = off;
#pragma unroll 8
        for (int m = 0; m < BCH; m++) {
            g_Cneg[(size_t)(b0 + m) * D + t] = run;
            run += sBQ[m * 64 + t];
        }
        if (chunk == NBCH - 1) g_Cneg[(size_t)NB * D + t] = run;
    } else if (t < 128) {
        int c0 = t - 64;
        float off = 0.f;
#pragma unroll
        for (int c = 0; c < NBCH; c++) {
            float v = __ldcg(&g_csumP[c * 64 + c0]);
            if (c > chunk) off += v;
        }
        float run = off;
        if (chunk == NBCH - 1) g_Cpos[(size_t)NB * D + c0] = 0.f;
#pragma unroll 8
        for (int m = BCH - 1; m >= 0; m--) {
            run += sBP[m * 64 + c0];
            g_Cpos[(size_t)(b0 + m) * D + c0] = run;
        }
    } else if (t == 128) {
        float off = 0.f;
#pragma unroll
        for (int c = 0; c < NBCH; c++) { float v = __ldcg(&g_csq[c]); if (c < chunk) off += v; }
        float run = off;
        for (int m = 0; m < BCH; m++) { g_Dneg[b0 + m] = run; run += sdq[m]; }
        if (chunk == NBCH - 1) g_Dneg[NB] = run;
    } else if (t == 129) {
        float off = 0.f;
#pragma unroll
        for (int c = 0; c < NBCH; c++) { float v = __ldcg(&g_csp[c]); if (c > chunk) off += v; }
        float run = off;
        if (chunk == NBCH - 1) g_Dpos[NB] = 0.f;
        for (int m = BCH - 1; m >= 0; m--) { run += sdp[m]; g_Dpos[b0 + m] = run; }
    }

    // replay-safe counter reset
    __syncthreads();
    if (t == 0) {
        int d = atomicAdd(&g_c2done, 1);
        if (d == NBCH - 1) { atomicExch(&g_c2, 0); atomicExch(&g_c2done, 0); }
    }
}

// =============== K4: per-row combine (1 warp/row, float2, packed members) ===============
// 1024 blocks x 256 threads; 8 rows/block
__global__ void __launch_bounds__(256, 6) k_out(float* __restrict__ out) {
    int t = threadIdx.x;
    int og = (t & 31) * 2;               // column pair
    int row = blockIdx.x * 8 + (t >> 5);

    float4 inf = g_rinfo[row];
    int   b   = __float_as_int(inf.x);
    float A   = inf.y, B = inf.z, thr = inf.w;

    float2 cp = *(const float2*)&g_Cpos[(size_t)(b + 1) * D + og];
    float2 cn = *(const float2*)&g_Cneg[(size_t)b * D + og];
    float dp = g_Dpos[b + 1], dn = g_Dneg[b];
    int cnt = g_cnt[b]; if (cnt > CAP) cnt = CAP;

    float2 num = make_float2(A * cp.x + B * cn.x, A * cp.y + B * cn.y);
    float den = A * dp + B * dn;

    for (int j = 0; j < cnt; j++) {      // exact compares within boundary bin (warp-uniform)
        float4 mp = g_mPack[b * CAP + j];          // single broadcast LDG.128
        int idx = __float_as_int(mp.x);
        float2 hv = *(const float2*)&g_h[(size_t)idx * D + og];
        float w = (mp.y >= thr) ? A * mp.z : B * mp.w;
        num.x = fmaf(w, hv.x, num.x);
        num.y = fmaf(w, hv.y, num.y);
        den += w;
    }

    float inv = 1.0f / den;
    float2 o2;
    float rx;
    rx = num.x * inv; o2.x = (rx > 0.f) ? rx : expm1f(rx);
    rx = num.y * inv; o2.y = (rx > 0.f) ? rx : expm1f(rx);
    *(float2*)&out[(size_t)row * D + og] = o2;
}

// ---------------- launch ----------------
extern "C" void kernel_launch(void* const* d_in, const int* in_sizes, int n_in,
                              void* d_out, int out_size) {
    const float* x  = (const float*)d_in[0];
    const float* Wt = (const float*)d_in[1];
    const float* a1 = (const float*)d_in[2];
    const float* b1 = (const float*)d_in[3];
    const float* a2 = (const float*)d_in[4];
    const float* b2 = (const float*)d_in[5];
    float* out = (float*)d_out;

    const int smem_scan = (2 * BCH * 64 + 2 * BCH) * 4;   // 33.3 KB

    static bool attr_set = false;
    if (!attr_set) {
        cudaFuncSetAttribute(k_binscan, cudaFuncAttributeMaxDynamicSharedMemorySize, smem_scan);
        attr_set = true;
    }

    k_feat<<<128, 1024>>>(x, Wt, a1, b1, a2, b2);
    k_binagg<<<64, 256>>>();
    k_binscan<<<NBCH, 256, smem_scan>>>();
    k_out<<<1024, 256>>>(out);
}